// round 6
// baseline (speedup 1.0000x reference)
#include <cuda_runtime.h>
#include <cstdint>
#include <cstddef>

// Problem shape (fixed by setup_inputs)
#define B_   8
#define S_   4096
#define D_   1024

// Tiling
#define NQ   4               // S-quarters per chain (cross-block split)
#define SQ   (S_ / NQ)       // 1024 timesteps per block
#define DT   32              // d-lanes per block
#define NW   8               // warps per block
#define CW   32              // timesteps per warp-subchunk
#define CT   (NW * CW)       // 256 timesteps per chunk
#define NC   (SQ / CT)       // 4 chunks per quarter
#define NTHR (NW * 32)       // 256 threads
#define SPAN (SQ / NTHR)     // 4 timesteps per thread in pos build
#define NCHAIN (B_ * (D_ / DT))   // 256 chains
#define NBLK   (NCHAIN * NQ)      // 1024 blocks

// Cross-block handoff state (cleared by clear_kernel each launch)
__device__ volatile int g_carry[NBLK];   // p_end+1 entering successor; 0 = not ready
__device__ volatile int g_sflag[NBLK];   // 1 = g_sval row valid
__device__ float        g_sval[NBLK][DT];

struct __align__(16) Smem {
    float  xbuf[2][CT][DT];       // 64 KB double-buffered x tile (xbuf[1] holds the
                                  //       id window during the prologue)
    float4 tbl[2][CT];            // 8 KB per-timestep (m, n, w, _), double-buffered
    float  aggL[NW][DT];          // per-warp local affine sums
    float  aggP[NW];              // per-warp carry-kill factors (0 or 1)
    unsigned short pos[SQ];       // 2 KB position-in-group (quarter-local, then exact)
    unsigned short spanEnd[NTHR];
    unsigned short spanCarry[NTHR];
    unsigned char  spanFR[NTHR];  // first-reset offset in span (SPAN = none)
    int    modeAcc;
    int    frqAcc;                // first reset index within quarter
    int    carryIn;
};

__device__ __forceinline__ unsigned smem_u32(const void* p) {
    return (unsigned)__cvta_generic_to_shared(p);
}
__device__ __forceinline__ void cp16(unsigned dst, const void* src) {
    asm volatile("cp.async.cg.shared.global [%0], [%1], 16;\n" :: "r"(dst), "l"(src));
}
__device__ __forceinline__ void cp_commit() {
    asm volatile("cp.async.commit_group;\n");
}
__device__ __forceinline__ void cp_wait0() {
    asm volatile("cp.async.wait_group 0;\n" ::: "memory");
}

__global__ void clear_kernel() {
    int i = blockIdx.x * blockDim.x + threadIdx.x;
    if (i < NBLK) { g_carry[i] = 0; g_sflag[i] = 0; }
}

// ---------------------------------------------------------------------------
// One block owns one quarter-chain: (batch b, 32-wide d-tile, SQ timesteps).
// blockIdx = q*NCHAIN + chain  (q-major: predecessors always dispatch earlier).
// ---------------------------------------------------------------------------
__global__ void __launch_bounds__(NTHR, 2)
pool_scan_kernel(const float* __restrict__ emb,
                 const int*   __restrict__ idw,   // raw 32-bit word view of ids
                 float* __restrict__ out)
{
    extern __shared__ char raw[];
    Smem* sm = reinterpret_cast<Smem*>(raw);

    const int bid   = blockIdx.x;
    const int chain = bid % NCHAIN;
    const int q     = bid / NCHAIN;

    const int tid = threadIdx.x;
    const int w   = tid >> 5;
    const int l   = tid & 31;

    const int ndt = D_ / DT;                    // 32 d-tiles
    const int b   = chain / ndt;
    const int d0  = (chain % ndt) * DT;

    const float* xg  = emb + ((size_t)b * S_ + q * SQ) * D_ + d0;
    float*       og0 = out + ((size_t)b * S_ + q * SQ) * D_ + d0;

    // ================= prologue =================
    if (tid == 0) { sm->modeAcc = 0; sm->frqAcc = 1 << 30; }

    // chunk 0 x-tile -> xbuf[0]
    #pragma unroll
    for (int k = 0; k < 8; k++) {
        int f   = tid + k * NTHR;
        int row = f >> 3, c4 = f & 7;
        cp16(smem_u32(&sm->xbuf[0][row][c4 * 4]),
             xg + (size_t)row * D_ + c4 * 4);
    }
    cp_commit();
    __syncthreads();   // modeAcc/frqAcc init visible

    // dtype detect via globally-safe window: words [0,4096) are in-bounds under
    // both interpretations; odd words are int64 hi-halves (all 0) iff int64.
    {
        int acc = 0;
        #pragma unroll
        for (int k = 0; k < 4; k++)
            acc |= __ldg(&idw[2 * (tid * 4 + k) + 1]);
        #pragma unroll
        for (int o = 16; o; o >>= 1) acc |= __shfl_xor_sync(~0u, acc, o);
        if (l == 0) atomicOr(&sm->modeAcc, acc);
    }
    __syncthreads();
    const bool mode64 = (sm->modeAcc == 0);

    // id window for this quarter -> xbuf[1] scratch
    int* scratch = (int*)&sm->xbuf[1][0][0];
    {
        const int wbase = b * S_ + q * SQ;      // element base
        if (mode64) {
            const int* wsrc = idw + 2 * (size_t)wbase;   // 2048 words
            #pragma unroll
            for (int k = 0; k < 2; k++) {
                int i4 = tid + k * NTHR;        // 512 int4
                cp16(smem_u32(scratch + i4 * 4), wsrc + i4 * 4);
            }
        } else {
            const int* wsrc = idw + (size_t)wbase;       // 1024 words
            cp16(smem_u32(scratch + tid * 4), wsrc + tid * 4);
        }
        cp_commit();
    }
    cp_wait0();
    __syncthreads();

    // --- pos build, pass A: each thread scans SPAN consecutive timesteps ---
    {
        const int base = tid * SPAN;
        int p = 0, fr = SPAN;
        #pragma unroll
        for (int j = 0; j < SPAN; j++) {
            int f;
            if (mode64) f = (scratch[2 * (base + j)] == 1) & (scratch[2 * (base + j) + 1] == 0);
            else        f = (scratch[base + j] == 1);
            p = f ? 1 : p + 1;
            if (f && fr == SPAN) fr = j;
            sm->pos[base + j] = (unsigned short)p;
        }
        sm->spanEnd[tid] = (unsigned short)p;
        sm->spanFR[tid]  = (unsigned char)fr;
        if (fr < SPAN) atomicMin(&sm->frqAcc, base + fr);
    }
    __syncthreads();

    // --- span scan (warp 0): carry = run length entering each span ---
    if (tid < 32) {
        int a = 0, bb = 1;
        #pragma unroll
        for (int k = 0; k < 8; k++) {
            int s  = tid * 8 + k;
            int hr = (sm->spanFR[s] < SPAN);
            int e  = sm->spanEnd[s];
            if (hr) { a = e; bb = 0; } else { a += SPAN; }
        }
        #pragma unroll
        for (int o = 1; o < 32; o <<= 1) {
            int pa = __shfl_up_sync(~0u, a,  o);
            int pb = __shfl_up_sync(~0u, bb, o);
            if (tid >= o) { a = a + bb * pa; bb = bb * pb; }
        }
        int ex = __shfl_up_sync(~0u, a, 1);
        if (tid == 0) ex = 0;
        int c = ex;
        #pragma unroll
        for (int k = 0; k < 8; k++) {
            int s = tid * 8 + k;
            sm->spanCarry[s] = (unsigned short)c;
            int hr = (sm->spanFR[s] < SPAN);
            c = hr ? (int)sm->spanEnd[s] : c + SPAN;
        }
    }
    __syncthreads();

    // --- pos build, pass B: intra-quarter span carries ---
    {
        const int base = tid * SPAN;
        int c  = sm->spanCarry[tid];
        int fr = sm->spanFR[tid];
        if (c) {
            #pragma unroll
            for (int j = 0; j < SPAN; j++)
                if (j < fr) sm->pos[base + j] = (unsigned short)(sm->pos[base + j] + c);
        }
    }
    __syncthreads();

    const int frq = min(sm->frqAcc, SQ);        // first reset within quarter

    // --- cross-block carry: wait predecessor's run length, correct head pos ---
    if (q > 0) {
        if (tid == 0) {
            int v;
            while ((v = g_carry[bid - NCHAIN]) == 0) __nanosleep(64);
            sm->carryIn = v - 1;
        }
        __syncthreads();
        int carry = sm->carryIn;
        for (int t = tid; t < frq; t += NTHR)
            sm->pos[t] = (unsigned short)(sm->pos[t] + carry);
        __syncthreads();
    }
    // publish own outgoing run length (single-word payload; fence for ordering)
    if (tid == 0) {
        __threadfence();
        g_carry[bid] = (int)sm->pos[SQ - 1] + 1;
    }

    // --- table for chunk 0 (positions now exact) ---
    {
        int p = sm->pos[tid];
        float pf = (float)p;
        sm->tbl[0][tid] = make_float4(p != 1 ? 1.0f : 0.0f, pf,
                                      __fdividef(1.0f, pf), 0.0f);
    }
    __syncthreads();

    // ================= main loop =================
    float cn = 0.f;                             // quarter-local affine sum
    const int tb = w * CW;

    for (int c = 0; c < NC; ++c) {
        const int cur = c & 1, nxt = cur ^ 1;
        const bool hasNext = (c + 1 < NC);

        if (hasNext) {
            const int t0n = (c + 1) * CT;
            #pragma unroll
            for (int k = 0; k < 8; k++) {
                int f   = tid + k * NTHR;
                int row = f >> 3, c4 = f & 7;
                cp16(smem_u32(&sm->xbuf[nxt][row][c4 * 4]),
                     xg + (size_t)(t0n + row) * D_ + c4 * 4);
            }
            cp_commit();
            int p = sm->pos[t0n + tid];
            float pf = (float)p;
            sm->tbl[nxt][tid] = make_float4(p != 1 ? 1.0f : 0.0f, pf,
                                            __fdividef(1.0f, pf), 0.0f);
        }

        // ---- pass 1: per-warp local affine sum ----
        float L = 0.f;
        #pragma unroll
        for (int j = 0; j < CW; ++j) {
            float x = sm->xbuf[cur][tb + j][l];
            float2 mn = *(const float2*)&sm->tbl[cur][tb + j];
            L = fmaf(L, mn.x, x * mn.y);
        }
        {
            int pl = sm->pos[c * CT + tb + l];
            unsigned msk = __ballot_sync(~0u, pl == 1);
            if (l == 0) sm->aggP[w] = msk ? 0.f : 1.f;
        }
        sm->aggL[w][l] = L;
        __syncthreads();

        // ---- combine ----
        float S = cn, in_S = cn;
        #pragma unroll
        for (int qq = 0; qq < NW; ++qq) {
            if (qq == w) in_S = S;
            S = fmaf(S, sm->aggP[qq], sm->aggL[qq][l]);
        }
        cn = S;

        // ---- pass 2: inclusive scan + write ----
        float Sv = in_S;
        float* ob = og0 + (size_t)(c * CT + tb) * D_ + l;
        #pragma unroll
        for (int j = 0; j < CW; ++j) {
            float x  = sm->xbuf[cur][tb + j][l];
            float4 t4 = sm->tbl[cur][tb + j];
            Sv = fmaf(Sv, t4.x, x * t4.y);
            ob[(size_t)j * D_] = Sv * t4.z;
        }

        if (hasNext) cp_wait0();
        __syncthreads();
    }

    // ================= epilogue: S handoff + head fixup =================
    const bool hasReset = (frq < SQ);

    // publish final S when exact without predecessor (q==0 always exact;
    // q>0 exact iff the quarter contains a reset)
    if (q == 0 || hasReset) {
        if (w == 0) g_sval[bid][l] = cn;
        __threadfence();
        if (tid == 0) g_sflag[bid] = 1;
    }

    if (q > 0) {
        if (tid == 0) {
            while (g_sflag[bid - NCHAIN] == 0) __nanosleep(64);
        }
        __syncthreads();
        __threadfence();
        const float S_in = g_sval[bid - NCHAIN][l];

        if (!hasReset) {          // rare: whole quarter is one run
            float Sf = S_in + cn; // m == 1 throughout
            if (w == 0) g_sval[bid][l] = Sf;
            __threadfence();
            if (tid == 0) g_sflag[bid] = 1;
        }

        // additive head fixup: rows before the quarter's first reset
        for (int t = w; t < frq; t += NW) {
            float wv = __fdividef(1.0f, (float)sm->pos[t]);
            float* p = og0 + (size_t)t * D_ + l;
            *p = *p + S_in * wv;
        }
    }
}

extern "C" void kernel_launch(void* const* d_in, const int* in_sizes, int n_in,
                              void* d_out, int out_size) {
    const float* emb = (const float*)d_in[0];
    const int*   idw = (const int*)d_in[1];
    float*       out = (float*)d_out;

    (void)in_sizes; (void)n_in; (void)out_size;

    cudaFuncSetAttribute(pool_scan_kernel,
                         cudaFuncAttributeMaxDynamicSharedMemorySize,
                         (int)sizeof(Smem));

    clear_kernel<<<(NBLK + 255) / 256, 256>>>();
    pool_scan_kernel<<<NBLK, NTHR, sizeof(Smem)>>>(emb, idw, out);
}

// round 7
// speedup vs baseline: 1.2689x; 1.2689x over previous
#include <cuda_runtime.h>
#include <cstdint>
#include <cstddef>

// Problem shape (fixed by setup_inputs)
#define B_   8
#define S_   4096
#define D_   1024

// Tiling
#define DT   32              // d-lanes per block
#define NW   8               // warps per block
#define CW   32              // timesteps per warp-subchunk
#define CT   (NW * CW)       // 256 timesteps per chunk
#define NC   (S_ / CT)       // 16 chunks per chain
#define NTHR (NW * 32)       // 256 threads
#define SPAN 16              // timesteps per thread in prologue pos build

struct __align__(16) Smem {
    float  xbuf[2][CT][DT];       // 64 KB double-buffered x tile (xbuf[1] holds the
                                  //       16 KB id window during the prologue)
    float4 tbl[2][CT];            // 8 KB per-timestep (m, n, w, c), double-buffered
    float  aggL[NW][DT];          // 1 KB per-warp local affine sums
    float  aggPb[2][NW];          // per-warp carry-kill factors (0 or 1), dbl-buffered
    unsigned short pos[S_];       // 8 KB position-in-group for the whole chain
    unsigned short spanEnd[NTHR];
    unsigned short spanCarry[NTHR];
    unsigned char  spanFR[NTHR];  // first-reset offset in span (SPAN = none)
    int    modeAcc;
};

__device__ __forceinline__ unsigned smem_u32(const void* p) {
    return (unsigned)__cvta_generic_to_shared(p);
}
__device__ __forceinline__ void cp16(unsigned dst, const void* src) {
    asm volatile("cp.async.cg.shared.global [%0], [%1], 16;\n" :: "r"(dst), "l"(src));
}
__device__ __forceinline__ void cp_commit() {
    asm volatile("cp.async.commit_group;\n");
}
__device__ __forceinline__ void cp_wait0() {
    asm volatile("cp.async.wait_group 0;\n" ::: "memory");
}

// Build the per-timestep table for chunk cc into buffer bb.
// Lanes of warp w map to timesteps of subchunk w, so one ballot gives both the
// suffix kill for c and the whole-subchunk kill factor P.
//   m = (pos!=1), n = pos, w = 1/pos, c = n if no reset strictly after this
//   timestep within its 32-step subchunk else 0.
__device__ __forceinline__ void build_tbl(Smem* sm, int bb, int cc,
                                          int tid, int w, int l) {
    int p = sm->pos[cc * CT + tid];
    float pf = (float)p;
    unsigned rmask = __ballot_sync(~0u, p == 1);
    unsigned above = rmask & ~((2u << l) - 1u);   // resets strictly after lane
    float cf = above ? 0.0f : pf;
    float m  = (p != 1) ? 1.0f : 0.0f;
    sm->tbl[bb][tid] = make_float4(m, pf, __fdividef(1.0f, pf), cf);
    if (l == 0) sm->aggPb[bb][w] = rmask ? 0.0f : 1.0f;
}

// ---------------------------------------------------------------------------
// One block owns one full chain: (batch b, 32-wide d-tile, all S).
// out[t] = S[t]*w[t],  S = S*m + x*n  (affine segmented scan); pass 1 uses the
// suffix-folded coefficients c so the warp-local sum is a plain dot product.
// ---------------------------------------------------------------------------
__global__ void __launch_bounds__(NTHR, 2)
pool_scan_kernel(const float* __restrict__ emb,
                 const int*   __restrict__ idw,   // raw 32-bit word view of ids
                 float* __restrict__ out)
{
    extern __shared__ char raw[];
    Smem* sm = reinterpret_cast<Smem*>(raw);

    const int tid = threadIdx.x;
    const int w   = tid >> 5;
    const int l   = tid & 31;

    const int ndt = D_ / DT;                    // 32 d-tiles
    const int b   = blockIdx.x / ndt;
    const int d0  = (blockIdx.x % ndt) * DT;

    const float* xg = emb + ((size_t)b * S_) * D_ + d0;
    float*       og = out + ((size_t)b * S_) * D_ + d0;

    // ================= prologue =================
    if (tid == 0) sm->modeAcc = 0;
    {
        // chunk 0 x-tile -> xbuf[0]
        #pragma unroll
        for (int k = 0; k < 8; k++) {
            int f   = tid + k * NTHR;
            int row = f >> 3, c4 = f & 7;
            cp16(smem_u32(&sm->xbuf[0][row][c4 * 4]),
                 xg + (size_t)row * D_ + c4 * 4);
        }
        // safe id window [b*S, b*S+S) words -> xbuf[1] scratch (in-bounds and
        // even-word-aligned under both dtype interpretations)
        const int* wsrc = idw + (size_t)b * S_;
        int* scratch = (int*)&sm->xbuf[1][0][0];
        #pragma unroll
        for (int k = 0; k < 4; k++) {
            int i4 = tid + k * NTHR;
            cp16(smem_u32(scratch + i4 * 4), wsrc + i4 * 4);
        }
        cp_commit();
    }
    cp_wait0();
    __syncthreads();

    // dtype detect: odd words of the window are all-zero iff int64 ids
    {
        const int* scratch = (const int*)&sm->xbuf[1][0][0];
        int acc = 0;
        #pragma unroll
        for (int k = 0; k < 8; k++)
            acc |= scratch[2 * (tid + k * NTHR) + 1];
        #pragma unroll
        for (int o = 16; o; o >>= 1) acc |= __shfl_xor_sync(~0u, acc, o);
        if (l == 0) atomicOr(&sm->modeAcc, acc);
    }
    __syncthreads();
    const bool mode64 = (sm->modeAcc == 0);

    // --- pos build, pass A: each thread scans SPAN consecutive timesteps ---
    {
        const int base = tid * SPAN;
        int p = 0, fr = SPAN;
        if (mode64) {
            const int2* q = ((const int2*)idw) + (size_t)b * S_ + base;
            #pragma unroll
            for (int j = 0; j < SPAN; j++) {
                int2 v = __ldg(&q[j]);
                int f = (v.x == 1) & (v.y == 0);
                p = f ? 1 : p + 1;
                if (f && fr == SPAN) fr = j;
                sm->pos[base + j] = (unsigned short)p;
            }
        } else {
            const int* sc = (const int*)&sm->xbuf[1][0][0];
            #pragma unroll
            for (int j = 0; j < SPAN; j++) {
                int f = (sc[base + j] == 1);
                p = f ? 1 : p + 1;
                if (f && fr == SPAN) fr = j;
                sm->pos[base + j] = (unsigned short)p;
            }
        }
        sm->spanEnd[tid] = (unsigned short)p;
        sm->spanFR[tid]  = (unsigned char)fr;
    }
    __syncthreads();

    // --- span scan (warp 0): carry = run length entering each span ---
    if (tid < 32) {
        int a = 0, bb = 1;
        #pragma unroll
        for (int k = 0; k < 8; k++) {
            int s  = tid * 8 + k;
            int hr = (sm->spanFR[s] < SPAN);
            int e  = sm->spanEnd[s];
            if (hr) { a = e; bb = 0; } else { a += SPAN; }
        }
        #pragma unroll
        for (int o = 1; o < 32; o <<= 1) {
            int pa = __shfl_up_sync(~0u, a,  o);
            int pb = __shfl_up_sync(~0u, bb, o);
            if (tid >= o) { a = a + bb * pa; bb = bb * pb; }
        }
        int ex = __shfl_up_sync(~0u, a, 1);
        if (tid == 0) ex = 0;
        int c = ex;
        #pragma unroll
        for (int k = 0; k < 8; k++) {
            int s = tid * 8 + k;
            sm->spanCarry[s] = (unsigned short)c;
            int hr = (sm->spanFR[s] < SPAN);
            c = hr ? (int)sm->spanEnd[s] : c + SPAN;
        }
    }
    __syncthreads();

    // --- pos build, pass B: add incoming carry to pre-first-reset prefix ---
    {
        const int base = tid * SPAN;
        int c  = sm->spanCarry[tid];
        int fr = sm->spanFR[tid];
        if (c) {
            #pragma unroll
            for (int j = 0; j < SPAN; j++)
                if (j < fr) sm->pos[base + j] = (unsigned short)(sm->pos[base + j] + c);
        }
    }
    __syncthreads();

    // --- table + kill factors for chunk 0 ---
    build_tbl(sm, 0, 0, tid, w, l);
    __syncthreads();

    // ================= main loop =================
    float cn = 0.f;                             // chain carry (affine sum)
    const int tb = w * CW;                      // warp's subchunk base in chunk

    for (int c = 0; c < NC; ++c) {
        const int cur = c & 1, nxt = cur ^ 1;
        const bool hasNext = (c + 1 < NC);

        if (hasNext) {
            const int t0n = (c + 1) * CT;
            #pragma unroll
            for (int k = 0; k < 8; k++) {
                int f   = tid + k * NTHR;
                int row = f >> 3, c4 = f & 7;
                cp16(smem_u32(&sm->xbuf[nxt][row][c4 * 4]),
                     xg + (size_t)(t0n + row) * D_ + c4 * 4);
            }
            cp_commit();
            build_tbl(sm, nxt, c + 1, tid, w, l);   // tbl[nxt] safe: last read
                                                    // before previous barrier
        }

        // ---- pass 1: warp-local dot product with folded coefficients ----
        float a0 = 0.f, a1 = 0.f, a2 = 0.f, a3 = 0.f;
        #pragma unroll
        for (int j = 0; j < CW; j += 4) {
            float x0 = sm->xbuf[cur][tb + j + 0][l];
            float x1 = sm->xbuf[cur][tb + j + 1][l];
            float x2 = sm->xbuf[cur][tb + j + 2][l];
            float x3 = sm->xbuf[cur][tb + j + 3][l];
            a0 = fmaf(x0, sm->tbl[cur][tb + j + 0].w, a0);
            a1 = fmaf(x1, sm->tbl[cur][tb + j + 1].w, a1);
            a2 = fmaf(x2, sm->tbl[cur][tb + j + 2].w, a2);
            a3 = fmaf(x3, sm->tbl[cur][tb + j + 3].w, a3);
        }
        sm->aggL[w][l] = (a0 + a1) + (a2 + a3);
        __syncthreads();

        // ---- combine: hoisted loads, then short FMA chain ----
        float Lq[NW], Pq[NW];
        #pragma unroll
        for (int q = 0; q < NW; ++q) {
            Lq[q] = sm->aggL[q][l];
            Pq[q] = sm->aggPb[cur][q];
        }
        float S = cn, in_S = cn;
        #pragma unroll
        for (int q = 0; q < NW; ++q) {
            if (q == w) in_S = S;
            S = fmaf(S, Pq[q], Lq[q]);
        }
        cn = S;

        // ---- pass 2: inclusive scan + write ----
        float Sv = in_S;
        float* ob = og + (size_t)(c * CT + tb) * D_ + l;
        #pragma unroll
        for (int j = 0; j < CW; ++j) {
            float x  = sm->xbuf[cur][tb + j][l];
            float4 t4 = sm->tbl[cur][tb + j];
            Sv = fmaf(Sv, t4.x, x * t4.y);
            ob[(size_t)j * D_] = Sv * t4.z;
        }

        if (hasNext) cp_wait0();
        __syncthreads();
    }
}

extern "C" void kernel_launch(void* const* d_in, const int* in_sizes, int n_in,
                              void* d_out, int out_size) {
    const float* emb = (const float*)d_in[0];
    const int*   idw = (const int*)d_in[1];
    float*       out = (float*)d_out;

    (void)in_sizes; (void)n_in; (void)out_size;

    cudaFuncSetAttribute(pool_scan_kernel,
                         cudaFuncAttributeMaxDynamicSharedMemorySize,
                         (int)sizeof(Smem));

    dim3 grid(B_ * (D_ / DT));   // 256 blocks, each owns a full (b, d-tile) chain
    pool_scan_kernel<<<grid, NTHR, sizeof(Smem)>>>(emb, idw, out);
}